// round 13
// baseline (speedup 1.0000x reference)
#include <cuda_runtime.h>
#include <cuda_fp16.h>
#include <cstdint>

// Problem constants
#define B_    16
#define CIN   256
#define COUT  128
#define HW    64
#define OHW   128
#define KDIM  1024        // k' = q*256 + ci   (q = ty*2+tx tap index)
#define KS    64          // k' per pipeline stage
#define NK    16          // KDIM / KS
#define XP    66          // padded spatial extent
#define NSTG  3
#define STG_BYTES 32768   // A 16KB + B 16KB per stage
#define NTILES 2048       // 32 spatial x 4 phase x 16 batch
#define NPERS  296        // persistent CTAs (148 SM x 2)

// Scratch
__device__ __align__(16) __half g_wsyn[(size_t)B_ * 4 * COUT * KDIM];
__device__ __align__(16) __half g_xc[(size_t)B_ * XP * XP * CIN];

#define SWZ(o) ((o) ^ (((o) >> 3) & 0x70))

static __device__ __forceinline__ void mma16816(float c[4], unsigned a0, unsigned a1,
                                                unsigned a2, unsigned a3,
                                                unsigned b0, unsigned b1) {
    asm volatile(
        "mma.sync.aligned.m16n8k16.row.col.f32.f16.f16.f32 "
        "{%0,%1,%2,%3}, {%4,%5,%6,%7}, {%8,%9}, {%0,%1,%2,%3};\n"
        : "+f"(c[0]), "+f"(c[1]), "+f"(c[2]), "+f"(c[3])
        : "r"(a0), "r"(a1), "r"(a2), "r"(a3), "r"(b0), "r"(b1));
}
static __device__ __forceinline__ void ldsm4(unsigned r[4], unsigned addr) {
    asm volatile("ldmatrix.sync.aligned.m8n8.x4.shared.b16 {%0,%1,%2,%3}, [%4];"
                 : "=r"(r[0]), "=r"(r[1]), "=r"(r[2]), "=r"(r[3]) : "r"(addr));
}
static __device__ __forceinline__ void cpasync16(unsigned dst, const void* src) {
    asm volatile("cp.async.cg.shared.global [%0], [%1], 16;" :: "r"(dst), "l"(src));
}

// ---------------------------------------------------------------------------
// Fused front-end: prep (blocks 0..1055) + weight synth (blocks 1056..1311).
// Synth uses the R5 mapping: consecutive threads -> consecutive read offsets
// (reads dominate synth traffic; writes are 16B scattered, acceptable).
// ---------------------------------------------------------------------------
#define PREP_BLOCKS (XP * B_)   // 1056

__global__ void __launch_bounds__(256) front_kernel(
    const float* __restrict__ x,
    const float* __restrict__ feature, const float* __restrict__ weight,
    const float* __restrict__ t0, const float* __restrict__ t1,
    const float* __restrict__ t2, const float* __restrict__ t3,
    const float* __restrict__ m0, const float* __restrict__ m1,
    const float* __restrict__ m2, const float* __restrict__ m3) {
    __shared__ __align__(16) __half sh[64 * 264];
    const int t = threadIdx.x;

    if (blockIdx.x < PREP_BLOCKS) {
        const int row = blockIdx.x % XP;
        const int b   = blockIdx.x / XP;
        __half* dst = g_xc + ((size_t)b * XP + row) * XP * CIN;

        if (row == 0 || row == XP - 1) {
            for (int i = t; i < XP * CIN / 8; i += 256)
                ((uint4*)dst)[i] = make_uint4(0, 0, 0, 0);
            return;
        }
        const int y = row - 1;
        const float* xr = x + (((size_t)b * CIN + t) * HW + y) * HW;
#pragma unroll
        for (int x4 = 0; x4 < 16; x4++) {
            float4 v = ((const float4*)xr)[x4];
            int xx = x4 * 4;
            sh[(xx + 0) * 264 + t] = __float2half(v.x);
            sh[(xx + 1) * 264 + t] = __float2half(v.y);
            sh[(xx + 2) * 264 + t] = __float2half(v.z);
            sh[(xx + 3) * 264 + t] = __float2half(v.w);
        }
        __syncthreads();
        {
            int col = 1 + (t >> 2);
            int ch  = (t & 3) * 64;
            uint4* d4 = (uint4*)(dst + (size_t)col * CIN + ch);
            const uint4* s4 = (const uint4*)(sh + (col - 1) * 264 + ch);
#pragma unroll
            for (int i = 0; i < 8; i++) d4[i] = s4[i];
        }
        if (t < 64) {
            int c = (t < 32) ? 0 : (XP - 1);
            ((uint4*)(dst + (size_t)c * CIN))[t & 31] = make_uint4(0, 0, 0, 0);
        }
    } else {
        __shared__ float sf[B_ * 4];
        if (t < B_ * 4) sf[t] = feature[t];
        __syncthreads();

        int idx = (blockIdx.x - PREP_BLOCKS) * 256 + t;
        int kx  = idx & 3;
        int ky  = (idx >> 2) & 3;
        int co  = (idx >> 4) & (COUT - 1);
        int ci0 = (idx >> 11) * 8;

        float w[8], a0[8], a1[8], a2[8], a3[8];
#pragma unroll
        for (int i = 0; i < 8; i++) {
            int ci  = ci0 + i;
            int off = (ci * COUT + co) * 16 + ky * 4 + kx;
            int mi  = ci * COUT + co;
            w[i]  = weight[off];
            a0[i] = t0[off] * m0[mi];
            a1[i] = t1[off] * m1[mi];
            a2[i] = t2[off] * m2[mi];
            a3[i] = t3[off] * m3[mi];
        }
        int py = 1 - (ky & 1);
        int px = 1 - (kx & 1);
        int dy = (py + 1 - ky) / 2;
        int dx = (px + 1 - kx) / 2;
        int ty = dy + 1 - py;
        int tx = dx + 1 - px;
        int p  = py * 2 + px;
        int q  = ty * 2 + tx;

        size_t base     = ((size_t)p * COUT + co) * KDIM + q * 256 + ci0;
        size_t stride_b = (size_t)4 * COUT * KDIM;
#pragma unroll
        for (int b = 0; b < B_; b++) {
            const float* f = sf + b * 4;
            __align__(16) __half h[8];
#pragma unroll
            for (int i = 0; i < 8; i++)
                h[i] = __float2half(w[i] + a0[i] * f[0] + a1[i] * f[1] +
                                    a2[i] * f[2] + a3[i] * f[3]);
            *(uint4*)(g_wsyn + b * stride_b + base) = *(uint4*)h;
        }
    }
}

// ---------------------------------------------------------------------------
// Persistent GEMM: 296 CTAs, each streaming ~7 tiles with a flattened stage
// sequence s -> (tile = s>>4, ks = s&15). The depth-2 cp.async lookahead
// crosses tile boundaries, so the pipeline never drains between tiles.
// CTA tile 128x128 (M=co, N=spatial), warp tile 64x32, 8 warps, 2 CTAs/SM.
// ---------------------------------------------------------------------------
__global__ void __launch_bounds__(256, 2)
deconv_mma_kernel(const float* __restrict__ bias,
                  const float* __restrict__ prelu_a,
                  float* __restrict__ out) {
    extern __shared__ __align__(1024) char smem[];
    const unsigned sb = (unsigned)__cvta_generic_to_shared(smem);
    const int tid  = threadIdx.x;
    const int lane = tid & 31;
    const int warp = tid >> 5;
    const int warp_m = warp >> 2;
    const int warp_n = warp & 3;

    const int tile0 = blockIdx.x;                       // 0..295
    const int ntc   = (NTILES - tile0 + NPERS - 1) / NPERS;
    const int total = ntc * NK;                         // flattened stages

    // Fragment row bases + validated cheap swizzle masks.
    unsigned araw[4], amask[4], braw[2], bmask[2];
#pragma unroll
    for (int mi = 0; mi < 4; mi++) {
        int row = warp_m * 64 + mi * 16 + (lane & 15);
        araw[mi]  = row * 128;
        amask[mi] = (row & 7) << 4;
    }
#pragma unroll
    for (int g = 0; g < 2; g++) {
        int rown = warp_n * 32 + g * 16 + (lane & 15);
        braw[g]  = rown * 128;
        bmask[g] = (rown & 7) << 4;
    }
    const unsigned kbl = (lane >> 4) * 16;

    float acc[4][4][4];
#pragma unroll
    for (int i = 0; i < 4; i++)
#pragma unroll
        for (int j = 0; j < 4; j++)
#pragma unroll
            for (int r = 0; r < 4; r++) acc[i][j][r] = 0.f;

    const float alpha = prelu_a[0];

    auto fill = [&](int s) {
        const int tau = tile0 + NPERS * (s >> 4);
        const int ks  = s & 15;
        const int n0  = (tau & 31) * 128;
        const int y0  = n0 >> 6;
        const int p   = (tau >> 5) & 3;
        const int bb_ = tau >> 7;
        const int py = p >> 1, px = p & 1;
        const __half* wb = g_wsyn + (size_t)(bb_ * 4 + p) * COUT * KDIM;
        const __half* xb = g_xc + (size_t)bb_ * XP * XP * CIN;

        const unsigned ab = sb + (s % NSTG) * STG_BYTES;
        const unsigned bbs = ab + 16384;
        const int k0 = ks * KS;
#pragma unroll
        for (int i = 0; i < 4; i++) {
            int seg = tid + i * 256;
            int co = seg >> 3, s8 = seg & 7;
            cpasync16(ab + SWZ(co * 128 + s8 * 16),
                      wb + (size_t)co * KDIM + k0 + s8 * 8);
        }
        const int q  = ks >> 2;
        const int ty = q >> 1, tx = q & 1;
        const int ci0 = (ks & 3) * 64;
#pragma unroll
        for (int i = 0; i < 4; i++) {
            int seg = tid + i * 256;
            int n = seg >> 3, s8 = seg & 7;
            int yy  = y0 + (n >> 6) + ty + py;
            int xx2 = (n & 63) + tx + px;
            cpasync16(bbs + SWZ(n * 128 + s8 * 16),
                      xb + ((size_t)yy * XP + xx2) * CIN + ci0 + s8 * 8);
        }
        asm volatile("cp.async.commit_group;" ::: "memory");
    };

    auto compute = [&](int buf) {
        const unsigned ab = sb + buf * STG_BYTES;
        const unsigned bb = ab + 16384;
#pragma unroll
        for (int kk = 0; kk < 4; kk++) {
            const unsigned kkb = kbl + kk * 32;
            unsigned afr[4][4], bfr[2][4];
#pragma unroll
            for (int mi = 0; mi < 4; mi++)
                ldsm4(afr[mi], ab + araw[mi] + (kkb ^ amask[mi]));
#pragma unroll
            for (int g = 0; g < 2; g++)
                ldsm4(bfr[g], bb + braw[g] + (kkb ^ bmask[g]));
#pragma unroll
            for (int mi = 0; mi < 4; mi++)
#pragma unroll
                for (int nj = 0; nj < 4; nj++)
                    mma16816(acc[mi][nj], afr[mi][0], afr[mi][1], afr[mi][2],
                             afr[mi][3], bfr[nj >> 1][nj & 1],
                             bfr[nj >> 1][(nj & 1) + 2]);
        }
    };

    auto epilogue = [&](int tau) {
        const int n0 = (tau & 31) * 128;
        const int p  = (tau >> 5) & 3;
        const int bb_ = tau >> 7;
        const int py = p >> 1, px = p & 1;
#pragma unroll
        for (int mi = 0; mi < 4; mi++) {
            const int rbase = warp_m * 64 + mi * 16 + (lane >> 2);
#pragma unroll
            for (int hm = 0; hm < 2; hm++) {
                const int co = rbase + hm * 8;
                const float bv = bias[co];
                float* obase = out + ((size_t)bb_ * COUT + co) * OHW * OHW;
#pragma unroll
                for (int nj = 0; nj < 4; nj++) {
#pragma unroll
                    for (int u = 0; u < 2; u++) {
                        int n  = n0 + warp_n * 32 + nj * 8 + (lane & 3) * 2 + u;
                        int y  = n >> 6;
                        int xx = n & 63;
                        int oy = 2 * y + py;
                        int ox = 2 * xx + px;
                        float v = acc[mi][nj][hm * 2 + u] + bv;
                        v = (v >= 0.f) ? v : alpha * v;
                        obase[oy * OHW + ox] = v;
                    }
                }
            }
        }
        // reset accumulators for the next tile
#pragma unroll
        for (int i = 0; i < 4; i++)
#pragma unroll
            for (int j = 0; j < 4; j++)
#pragma unroll
                for (int r = 0; r < 4; r++) acc[i][j][r] = 0.f;
    };

    fill(0);
    fill(1);
    for (int s = 0; s < total; s++) {
        if (s == total - 1)
            asm volatile("cp.async.wait_group 0;" ::: "memory");
        else
            asm volatile("cp.async.wait_group 1;" ::: "memory");
        __syncthreads();
        if (s + 2 < total) fill(s + 2);
        compute(s % NSTG);
        if ((s & 15) == 15) epilogue(tile0 + NPERS * (s >> 4));
    }
}

// ---------------------------------------------------------------------------
// Launch
// ---------------------------------------------------------------------------
extern "C" void kernel_launch(void* const* d_in, const int* in_sizes, int n_in,
                              void* d_out, int out_size) {
    const float* x       = (const float*)d_in[0];
    const float* feature = (const float*)d_in[1];
    const float* weight  = (const float*)d_in[2];
    const float* t0      = (const float*)d_in[3];
    const float* t1      = (const float*)d_in[4];
    const float* t2      = (const float*)d_in[5];
    const float* t3      = (const float*)d_in[6];
    const float* m0      = (const float*)d_in[7];
    const float* m1      = (const float*)d_in[8];
    const float* m2      = (const float*)d_in[9];
    const float* m3      = (const float*)d_in[10];
    const float* bias    = (const float*)d_in[11];
    const float* prelu_a = (const float*)d_in[12];
    float* out = (float*)d_out;

    {
        int blocks = PREP_BLOCKS + (CIN / 8) * COUT * 16 / 256;  // 1056 + 256
        front_kernel<<<blocks, 256>>>(x, feature, weight, t0, t1, t2, t3,
                                      m0, m1, m2, m3);
    }
    {
        cudaFuncSetAttribute(deconv_mma_kernel,
                             cudaFuncAttributeMaxDynamicSharedMemorySize,
                             NSTG * STG_BYTES);
        deconv_mma_kernel<<<NPERS, 256, NSTG * STG_BYTES>>>(bias, prelu_a, out);
    }
}

// round 14
// speedup vs baseline: 1.0033x; 1.0033x over previous
#include <cuda_runtime.h>
#include <cuda_fp16.h>
#include <cstdint>

// Problem constants
#define B_    16
#define CIN   256
#define COUT  128
#define HW    64
#define OHW   128
#define KDIM  1024        // k' = q*256 + ci   (q = ty*2+tx tap index)
#define KS    64          // k' per pipeline stage
#define NK    16          // KDIM / KS
#define XP    66          // padded spatial extent
#define NSTG  3
#define STG_BYTES 32768   // A 16KB + B 16KB per stage
#define NTILES 2048       // 32 spatial x 4 phase x 16 batch
#define NPERS  296        // persistent CTAs (148 SM x 2)

// Scratch
__device__ __align__(16) __half g_wsyn[(size_t)B_ * 4 * COUT * KDIM];
__device__ __align__(16) __half g_xc[(size_t)B_ * XP * XP * CIN];

#define SWZ(o) ((o) ^ (((o) >> 3) & 0x70))

static __device__ __forceinline__ void mma16816(float c[4], unsigned a0, unsigned a1,
                                                unsigned a2, unsigned a3,
                                                unsigned b0, unsigned b1) {
    asm volatile(
        "mma.sync.aligned.m16n8k16.row.col.f32.f16.f16.f32 "
        "{%0,%1,%2,%3}, {%4,%5,%6,%7}, {%8,%9}, {%0,%1,%2,%3};\n"
        : "+f"(c[0]), "+f"(c[1]), "+f"(c[2]), "+f"(c[3])
        : "r"(a0), "r"(a1), "r"(a2), "r"(a3), "r"(b0), "r"(b1));
}
static __device__ __forceinline__ void ldsm4(unsigned r[4], unsigned addr) {
    asm volatile("ldmatrix.sync.aligned.m8n8.x4.shared.b16 {%0,%1,%2,%3}, [%4];"
                 : "=r"(r[0]), "=r"(r[1]), "=r"(r[2]), "=r"(r[3]) : "r"(addr));
}
static __device__ __forceinline__ void cpasync16(unsigned dst, const void* src) {
    asm volatile("cp.async.cg.shared.global [%0], [%1], 16;" :: "r"(dst), "l"(src));
}

// ---------------------------------------------------------------------------
// Fused front-end: prep (blocks 0..1055) + weight synth (blocks 1056..1311).
// Synth uses the R5 mapping: consecutive threads -> consecutive read offsets
// (reads dominate synth traffic; writes are 16B scattered, acceptable).
// ---------------------------------------------------------------------------
#define PREP_BLOCKS (XP * B_)   // 1056

__global__ void __launch_bounds__(256) front_kernel(
    const float* __restrict__ x,
    const float* __restrict__ feature, const float* __restrict__ weight,
    const float* __restrict__ t0, const float* __restrict__ t1,
    const float* __restrict__ t2, const float* __restrict__ t3,
    const float* __restrict__ m0, const float* __restrict__ m1,
    const float* __restrict__ m2, const float* __restrict__ m3) {
    __shared__ __align__(16) __half sh[64 * 264];
    const int t = threadIdx.x;

    if (blockIdx.x < PREP_BLOCKS) {
        const int row = blockIdx.x % XP;
        const int b   = blockIdx.x / XP;
        __half* dst = g_xc + ((size_t)b * XP + row) * XP * CIN;

        if (row == 0 || row == XP - 1) {
            for (int i = t; i < XP * CIN / 8; i += 256)
                ((uint4*)dst)[i] = make_uint4(0, 0, 0, 0);
            return;
        }
        const int y = row - 1;
        const float* xr = x + (((size_t)b * CIN + t) * HW + y) * HW;
#pragma unroll
        for (int x4 = 0; x4 < 16; x4++) {
            float4 v = ((const float4*)xr)[x4];
            int xx = x4 * 4;
            sh[(xx + 0) * 264 + t] = __float2half(v.x);
            sh[(xx + 1) * 264 + t] = __float2half(v.y);
            sh[(xx + 2) * 264 + t] = __float2half(v.z);
            sh[(xx + 3) * 264 + t] = __float2half(v.w);
        }
        __syncthreads();
        {
            int col = 1 + (t >> 2);
            int ch  = (t & 3) * 64;
            uint4* d4 = (uint4*)(dst + (size_t)col * CIN + ch);
            const uint4* s4 = (const uint4*)(sh + (col - 1) * 264 + ch);
#pragma unroll
            for (int i = 0; i < 8; i++) d4[i] = s4[i];
        }
        if (t < 64) {
            int c = (t < 32) ? 0 : (XP - 1);
            ((uint4*)(dst + (size_t)c * CIN))[t & 31] = make_uint4(0, 0, 0, 0);
        }
    } else {
        __shared__ float sf[B_ * 4];
        if (t < B_ * 4) sf[t] = feature[t];
        __syncthreads();

        int idx = (blockIdx.x - PREP_BLOCKS) * 256 + t;
        int kx  = idx & 3;
        int ky  = (idx >> 2) & 3;
        int co  = (idx >> 4) & (COUT - 1);
        int ci0 = (idx >> 11) * 8;

        float w[8], a0[8], a1[8], a2[8], a3[8];
#pragma unroll
        for (int i = 0; i < 8; i++) {
            int ci  = ci0 + i;
            int off = (ci * COUT + co) * 16 + ky * 4 + kx;
            int mi  = ci * COUT + co;
            w[i]  = weight[off];
            a0[i] = t0[off] * m0[mi];
            a1[i] = t1[off] * m1[mi];
            a2[i] = t2[off] * m2[mi];
            a3[i] = t3[off] * m3[mi];
        }
        int py = 1 - (ky & 1);
        int px = 1 - (kx & 1);
        int dy = (py + 1 - ky) / 2;
        int dx = (px + 1 - kx) / 2;
        int ty = dy + 1 - py;
        int tx = dx + 1 - px;
        int p  = py * 2 + px;
        int q  = ty * 2 + tx;

        size_t base     = ((size_t)p * COUT + co) * KDIM + q * 256 + ci0;
        size_t stride_b = (size_t)4 * COUT * KDIM;
#pragma unroll
        for (int b = 0; b < B_; b++) {
            const float* f = sf + b * 4;
            __align__(16) __half h[8];
#pragma unroll
            for (int i = 0; i < 8; i++)
                h[i] = __float2half(w[i] + a0[i] * f[0] + a1[i] * f[1] +
                                    a2[i] * f[2] + a3[i] * f[3]);
            *(uint4*)(g_wsyn + b * stride_b + base) = *(uint4*)h;
        }
    }
}

// ---------------------------------------------------------------------------
// Persistent GEMM: 296 CTAs, each streaming ~7 tiles with a flattened stage
// sequence s -> (tile = s>>4, ks = s&15). The depth-2 cp.async lookahead
// crosses tile boundaries, so the pipeline never drains between tiles.
// CTA tile 128x128 (M=co, N=spatial), warp tile 64x32, 8 warps, 2 CTAs/SM.
// ---------------------------------------------------------------------------
__global__ void __launch_bounds__(256, 2)
deconv_mma_kernel(const float* __restrict__ bias,
                  const float* __restrict__ prelu_a,
                  float* __restrict__ out) {
    extern __shared__ __align__(1024) char smem[];
    const unsigned sb = (unsigned)__cvta_generic_to_shared(smem);
    const int tid  = threadIdx.x;
    const int lane = tid & 31;
    const int warp = tid >> 5;
    const int warp_m = warp >> 2;
    const int warp_n = warp & 3;

    const int tile0 = blockIdx.x;                       // 0..295
    const int ntc   = (NTILES - tile0 + NPERS - 1) / NPERS;
    const int total = ntc * NK;                         // flattened stages

    // Fragment row bases + validated cheap swizzle masks.
    unsigned araw[4], amask[4], braw[2], bmask[2];
#pragma unroll
    for (int mi = 0; mi < 4; mi++) {
        int row = warp_m * 64 + mi * 16 + (lane & 15);
        araw[mi]  = row * 128;
        amask[mi] = (row & 7) << 4;
    }
#pragma unroll
    for (int g = 0; g < 2; g++) {
        int rown = warp_n * 32 + g * 16 + (lane & 15);
        braw[g]  = rown * 128;
        bmask[g] = (rown & 7) << 4;
    }
    const unsigned kbl = (lane >> 4) * 16;

    float acc[4][4][4];
#pragma unroll
    for (int i = 0; i < 4; i++)
#pragma unroll
        for (int j = 0; j < 4; j++)
#pragma unroll
            for (int r = 0; r < 4; r++) acc[i][j][r] = 0.f;

    const float alpha = prelu_a[0];

    auto fill = [&](int s) {
        const int tau = tile0 + NPERS * (s >> 4);
        const int ks  = s & 15;
        const int n0  = (tau & 31) * 128;
        const int y0  = n0 >> 6;
        const int p   = (tau >> 5) & 3;
        const int bb_ = tau >> 7;
        const int py = p >> 1, px = p & 1;
        const __half* wb = g_wsyn + (size_t)(bb_ * 4 + p) * COUT * KDIM;
        const __half* xb = g_xc + (size_t)bb_ * XP * XP * CIN;

        const unsigned ab = sb + (s % NSTG) * STG_BYTES;
        const unsigned bbs = ab + 16384;
        const int k0 = ks * KS;
#pragma unroll
        for (int i = 0; i < 4; i++) {
            int seg = tid + i * 256;
            int co = seg >> 3, s8 = seg & 7;
            cpasync16(ab + SWZ(co * 128 + s8 * 16),
                      wb + (size_t)co * KDIM + k0 + s8 * 8);
        }
        const int q  = ks >> 2;
        const int ty = q >> 1, tx = q & 1;
        const int ci0 = (ks & 3) * 64;
#pragma unroll
        for (int i = 0; i < 4; i++) {
            int seg = tid + i * 256;
            int n = seg >> 3, s8 = seg & 7;
            int yy  = y0 + (n >> 6) + ty + py;
            int xx2 = (n & 63) + tx + px;
            cpasync16(bbs + SWZ(n * 128 + s8 * 16),
                      xb + ((size_t)yy * XP + xx2) * CIN + ci0 + s8 * 8);
        }
        asm volatile("cp.async.commit_group;" ::: "memory");
    };

    auto compute = [&](int buf) {
        const unsigned ab = sb + buf * STG_BYTES;
        const unsigned bb = ab + 16384;
#pragma unroll
        for (int kk = 0; kk < 4; kk++) {
            const unsigned kkb = kbl + kk * 32;
            unsigned afr[4][4], bfr[2][4];
#pragma unroll
            for (int mi = 0; mi < 4; mi++)
                ldsm4(afr[mi], ab + araw[mi] + (kkb ^ amask[mi]));
#pragma unroll
            for (int g = 0; g < 2; g++)
                ldsm4(bfr[g], bb + braw[g] + (kkb ^ bmask[g]));
#pragma unroll
            for (int mi = 0; mi < 4; mi++)
#pragma unroll
                for (int nj = 0; nj < 4; nj++)
                    mma16816(acc[mi][nj], afr[mi][0], afr[mi][1], afr[mi][2],
                             afr[mi][3], bfr[nj >> 1][nj & 1],
                             bfr[nj >> 1][(nj & 1) + 2]);
        }
    };

    auto epilogue = [&](int tau) {
        const int n0 = (tau & 31) * 128;
        const int p  = (tau >> 5) & 3;
        const int bb_ = tau >> 7;
        const int py = p >> 1, px = p & 1;
#pragma unroll
        for (int mi = 0; mi < 4; mi++) {
            const int rbase = warp_m * 64 + mi * 16 + (lane >> 2);
#pragma unroll
            for (int hm = 0; hm < 2; hm++) {
                const int co = rbase + hm * 8;
                const float bv = bias[co];
                float* obase = out + ((size_t)bb_ * COUT + co) * OHW * OHW;
#pragma unroll
                for (int nj = 0; nj < 4; nj++) {
#pragma unroll
                    for (int u = 0; u < 2; u++) {
                        int n  = n0 + warp_n * 32 + nj * 8 + (lane & 3) * 2 + u;
                        int y  = n >> 6;
                        int xx = n & 63;
                        int oy = 2 * y + py;
                        int ox = 2 * xx + px;
                        float v = acc[mi][nj][hm * 2 + u] + bv;
                        v = (v >= 0.f) ? v : alpha * v;
                        obase[oy * OHW + ox] = v;
                    }
                }
            }
        }
        // reset accumulators for the next tile
#pragma unroll
        for (int i = 0; i < 4; i++)
#pragma unroll
            for (int j = 0; j < 4; j++)
#pragma unroll
                for (int r = 0; r < 4; r++) acc[i][j][r] = 0.f;
    };

    fill(0);
    fill(1);
    for (int s = 0; s < total; s++) {
        if (s == total - 1)
            asm volatile("cp.async.wait_group 0;" ::: "memory");
        else
            asm volatile("cp.async.wait_group 1;" ::: "memory");
        __syncthreads();
        if (s + 2 < total) fill(s + 2);
        compute(s % NSTG);
        if ((s & 15) == 15) epilogue(tile0 + NPERS * (s >> 4));
    }
}

// ---------------------------------------------------------------------------
// Launch
// ---------------------------------------------------------------------------
extern "C" void kernel_launch(void* const* d_in, const int* in_sizes, int n_in,
                              void* d_out, int out_size) {
    const float* x       = (const float*)d_in[0];
    const float* feature = (const float*)d_in[1];
    const float* weight  = (const float*)d_in[2];
    const float* t0      = (const float*)d_in[3];
    const float* t1      = (const float*)d_in[4];
    const float* t2      = (const float*)d_in[5];
    const float* t3      = (const float*)d_in[6];
    const float* m0      = (const float*)d_in[7];
    const float* m1      = (const float*)d_in[8];
    const float* m2      = (const float*)d_in[9];
    const float* m3      = (const float*)d_in[10];
    const float* bias    = (const float*)d_in[11];
    const float* prelu_a = (const float*)d_in[12];
    float* out = (float*)d_out;

    {
        int blocks = PREP_BLOCKS + (CIN / 8) * COUT * 16 / 256;  // 1056 + 256
        front_kernel<<<blocks, 256>>>(x, feature, weight, t0, t1, t2, t3,
                                      m0, m1, m2, m3);
    }
    {
        cudaFuncSetAttribute(deconv_mma_kernel,
                             cudaFuncAttributeMaxDynamicSharedMemorySize,
                             NSTG * STG_BYTES);
        deconv_mma_kernel<<<NPERS, 256, NSTG * STG_BYTES>>>(bias, prelu_a, out);
    }
}

// round 15
// speedup vs baseline: 1.0903x; 1.0867x over previous
#include <cuda_runtime.h>
#include <cuda_fp16.h>
#include <cstdint>

// Problem constants
#define B_    16
#define CIN   256
#define COUT  128
#define HW    64
#define OHW   128
#define KDIM  1024        // k' = q*256 + ci   (q = ty*2+tx tap index)
#define KS    64          // k' per pipeline stage
#define NK    16          // KDIM / KS
#define XP    66          // padded spatial extent
#define NSTG  3
#define STG_BYTES 32768   // A 16KB + B 16KB per stage

// Scratch
__device__ __align__(16) __half g_wsyn[(size_t)B_ * 4 * COUT * KDIM];
__device__ __align__(16) __half g_xc[(size_t)B_ * XP * XP * CIN];

#define SWZ(o) ((o) ^ (((o) >> 3) & 0x70))

static __device__ __forceinline__ void mma16816(float c[4], unsigned a0, unsigned a1,
                                                unsigned a2, unsigned a3,
                                                unsigned b0, unsigned b1) {
    asm volatile(
        "mma.sync.aligned.m16n8k16.row.col.f32.f16.f16.f32 "
        "{%0,%1,%2,%3}, {%4,%5,%6,%7}, {%8,%9}, {%0,%1,%2,%3};\n"
        : "+f"(c[0]), "+f"(c[1]), "+f"(c[2]), "+f"(c[3])
        : "r"(a0), "r"(a1), "r"(a2), "r"(a3), "r"(b0), "r"(b1));
}
static __device__ __forceinline__ void ldsm4(unsigned r[4], unsigned addr) {
    asm volatile("ldmatrix.sync.aligned.m8n8.x4.shared.b16 {%0,%1,%2,%3}, [%4];"
                 : "=r"(r[0]), "=r"(r[1]), "=r"(r[2]), "=r"(r[3]) : "r"(addr));
}
static __device__ __forceinline__ void cpasync16(unsigned dst, const void* src) {
    asm volatile("cp.async.cg.shared.global [%0], [%1], 16;" :: "r"(dst), "l"(src));
}

// ---------------------------------------------------------------------------
// Fused front-end, INTERLEAVED: grid 1320.
//   blockIdx % 5 == 2  -> synth block sid = blockIdx/5 (264 slots, 256 used)
//   otherwise          -> prep block  pid = blockIdx - (blockIdx+2)/5 (1056)
// Interleaving lets DRAM-bound prep and compute/scatter-bound synth co-run
// instead of synth forming a serialized tail wave.
// ---------------------------------------------------------------------------
#define FRONT_BLOCKS 1320

__global__ void __launch_bounds__(256) front_kernel(
    const float* __restrict__ x,
    const float* __restrict__ feature, const float* __restrict__ weight,
    const float* __restrict__ t0, const float* __restrict__ t1,
    const float* __restrict__ t2, const float* __restrict__ t3,
    const float* __restrict__ m0, const float* __restrict__ m1,
    const float* __restrict__ m2, const float* __restrict__ m3) {
    __shared__ __align__(16) __half sh[64 * 264];
    const int t = threadIdx.x;
    const int bidx = blockIdx.x;

    if (bidx % 5 != 2) {
        // ---------------- prep ----------------
        const int pid = bidx - (bidx + 2) / 5;   // 0..1055
        const int row = pid % XP;
        const int b   = pid / XP;
        __half* dst = g_xc + ((size_t)b * XP + row) * XP * CIN;

        if (row == 0 || row == XP - 1) {
            for (int i = t; i < XP * CIN / 8; i += 256)
                ((uint4*)dst)[i] = make_uint4(0, 0, 0, 0);
            return;
        }
        const int y = row - 1;
        const float* xr = x + (((size_t)b * CIN + t) * HW + y) * HW;
#pragma unroll
        for (int x4 = 0; x4 < 16; x4++) {
            float4 v = ((const float4*)xr)[x4];
            int xx = x4 * 4;
            sh[(xx + 0) * 264 + t] = __float2half(v.x);
            sh[(xx + 1) * 264 + t] = __float2half(v.y);
            sh[(xx + 2) * 264 + t] = __float2half(v.z);
            sh[(xx + 3) * 264 + t] = __float2half(v.w);
        }
        __syncthreads();
        {
            int col = 1 + (t >> 2);
            int ch  = (t & 3) * 64;
            uint4* d4 = (uint4*)(dst + (size_t)col * CIN + ch);
            const uint4* s4 = (const uint4*)(sh + (col - 1) * 264 + ch);
#pragma unroll
            for (int i = 0; i < 8; i++) d4[i] = s4[i];
        }
        if (t < 64) {
            int c = (t < 32) ? 0 : (XP - 1);
            ((uint4*)(dst + (size_t)c * CIN))[t & 31] = make_uint4(0, 0, 0, 0);
        }
    } else {
        // ---------------- synth (R5 coalesced-read mapping) ----------------
        const int sid = bidx / 5;                // 0..263
        if (sid >= 256) return;
        __shared__ float sf[B_ * 4];
        if (t < B_ * 4) sf[t] = feature[t];
        __syncthreads();

        int idx = sid * 256 + t;                 // over 32 ci-blocks*128co*16taps
        int kx  = idx & 3;
        int ky  = (idx >> 2) & 3;
        int co  = (idx >> 4) & (COUT - 1);
        int ci0 = (idx >> 11) * 8;

        float w[8], a0[8], a1[8], a2[8], a3[8];
#pragma unroll
        for (int i = 0; i < 8; i++) {
            int ci  = ci0 + i;
            int off = (ci * COUT + co) * 16 + ky * 4 + kx;
            int mi  = ci * COUT + co;
            w[i]  = weight[off];
            a0[i] = t0[off] * m0[mi];
            a1[i] = t1[off] * m1[mi];
            a2[i] = t2[off] * m2[mi];
            a3[i] = t3[off] * m3[mi];
        }
        int py = 1 - (ky & 1);
        int px = 1 - (kx & 1);
        int dy = (py + 1 - ky) / 2;
        int dx = (px + 1 - kx) / 2;
        int ty = dy + 1 - py;
        int tx = dx + 1 - px;
        int p  = py * 2 + px;
        int q  = ty * 2 + tx;

        size_t base     = ((size_t)p * COUT + co) * KDIM + q * 256 + ci0;
        size_t stride_b = (size_t)4 * COUT * KDIM;
#pragma unroll
        for (int b = 0; b < B_; b++) {
            const float* f = sf + b * 4;
            __align__(16) __half h[8];
#pragma unroll
            for (int i = 0; i < 8; i++)
                h[i] = __float2half(w[i] + a0[i] * f[0] + a1[i] * f[1] +
                                    a2[i] * f[2] + a3[i] * f[3]);
            *(uint4*)(g_wsyn + b * stride_b + base) = *(uint4*)h;
        }
    }
}

// ---------------------------------------------------------------------------
// GEMM (champion config, verified 234.0us): mma.sync m16n8k16, 3-stage
// cp.async pipeline, CTA 128x128, warp tile 64x32, 8 warps, 2 CTAs/SM.
// Cheap validated swizzle: SWZ(row*128+kb) = row*128 + (kb ^ ((row&7)<<4)).
// ---------------------------------------------------------------------------
__global__ void __launch_bounds__(256, 2)
deconv_mma_kernel(const float* __restrict__ bias,
                  const float* __restrict__ prelu_a,
                  float* __restrict__ out) {
    extern __shared__ __align__(1024) char smem[];
    const unsigned sb = (unsigned)__cvta_generic_to_shared(smem);
    const int tid  = threadIdx.x;
    const int lane = tid & 31;
    const int warp = tid >> 5;
    const int warp_m = warp >> 2;
    const int warp_n = warp & 3;
    const int b  = blockIdx.z;
    const int p  = blockIdx.y;
    const int py = p >> 1, px = p & 1;
    const int n0 = blockIdx.x * 128;
    const int y0 = n0 >> 6;

    const __half* wb = g_wsyn + (size_t)(b * 4 + p) * COUT * KDIM;
    const __half* xb = g_xc + (size_t)b * XP * XP * CIN;

    unsigned araw[4], amask[4], braw[2], bmask[2];
#pragma unroll
    for (int mi = 0; mi < 4; mi++) {
        int row = warp_m * 64 + mi * 16 + (lane & 15);
        araw[mi]  = row * 128;
        amask[mi] = (row & 7) << 4;
    }
#pragma unroll
    for (int g = 0; g < 2; g++) {
        int rown = warp_n * 32 + g * 16 + (lane & 15);
        braw[g]  = rown * 128;
        bmask[g] = (rown & 7) << 4;
    }
    const unsigned kbl = (lane >> 4) * 16;

    float acc[4][4][4];
#pragma unroll
    for (int i = 0; i < 4; i++)
#pragma unroll
        for (int j = 0; j < 4; j++)
#pragma unroll
            for (int r = 0; r < 4; r++) acc[i][j][r] = 0.f;

    auto fill = [&](int ks, int buf) {
        const unsigned ab = sb + buf * STG_BYTES;
        const unsigned bb = ab + 16384;
        const int k0 = ks * KS;
#pragma unroll
        for (int i = 0; i < 4; i++) {
            int seg = tid + i * 256;
            int co = seg >> 3, s8 = seg & 7;
            cpasync16(ab + SWZ(co * 128 + s8 * 16),
                      wb + (size_t)co * KDIM + k0 + s8 * 8);
        }
        const int q  = ks >> 2;
        const int ty = q >> 1, tx = q & 1;
        const int ci0 = (ks & 3) * 64;
#pragma unroll
        for (int i = 0; i < 4; i++) {
            int seg = tid + i * 256;
            int n = seg >> 3, s8 = seg & 7;
            int yy  = y0 + (n >> 6) + ty + py;
            int xx2 = (n & 63) + tx + px;
            cpasync16(bb + SWZ(n * 128 + s8 * 16),
                      xb + ((size_t)yy * XP + xx2) * CIN + ci0 + s8 * 8);
        }
        asm volatile("cp.async.commit_group;" ::: "memory");
    };

    auto compute = [&](int buf) {
        const unsigned ab = sb + buf * STG_BYTES;
        const unsigned bb = ab + 16384;
#pragma unroll
        for (int kk = 0; kk < 4; kk++) {
            const unsigned kkb = kbl + kk * 32;
            unsigned afr[4][4], bfr[2][4];
#pragma unroll
            for (int mi = 0; mi < 4; mi++)
                ldsm4(afr[mi], ab + araw[mi] + (kkb ^ amask[mi]));
#pragma unroll
            for (int g = 0; g < 2; g++)
                ldsm4(bfr[g], bb + braw[g] + (kkb ^ bmask[g]));
#pragma unroll
            for (int mi = 0; mi < 4; mi++)
#pragma unroll
                for (int nj = 0; nj < 4; nj++)
                    mma16816(acc[mi][nj], afr[mi][0], afr[mi][1], afr[mi][2],
                             afr[mi][3], bfr[nj >> 1][nj & 1],
                             bfr[nj >> 1][(nj & 1) + 2]);
        }
    };

    fill(0, 0);
    fill(1, 1);
    for (int ks = 0; ks < NK; ks++) {
        if (ks == NK - 1)
            asm volatile("cp.async.wait_group 0;" ::: "memory");
        else
            asm volatile("cp.async.wait_group 1;" ::: "memory");
        __syncthreads();
        if (ks + 2 < NK) fill(ks + 2, (ks + 2) % NSTG);
        compute(ks % NSTG);
    }

    // --- epilogue: bias + PReLU + stride-2 phase scatter ---
    const float alpha = prelu_a[0];
#pragma unroll
    for (int mi = 0; mi < 4; mi++) {
        const int rbase = warp_m * 64 + mi * 16 + (lane >> 2);
#pragma unroll
        for (int hm = 0; hm < 2; hm++) {
            const int co = rbase + hm * 8;
            const float bv = bias[co];
            float* obase = out + ((size_t)b * COUT + co) * OHW * OHW;
#pragma unroll
            for (int nj = 0; nj < 4; nj++) {
#pragma unroll
                for (int u = 0; u < 2; u++) {
                    int n  = n0 + warp_n * 32 + nj * 8 + (lane & 3) * 2 + u;
                    int y  = n >> 6;
                    int xx = n & 63;
                    int oy = 2 * y + py;
                    int ox = 2 * xx + px;
                    float v = acc[mi][nj][hm * 2 + u] + bv;
                    v = (v >= 0.f) ? v : alpha * v;
                    obase[oy * OHW + ox] = v;
                }
            }
        }
    }
}

// ---------------------------------------------------------------------------
// Launch
// ---------------------------------------------------------------------------
extern "C" void kernel_launch(void* const* d_in, const int* in_sizes, int n_in,
                              void* d_out, int out_size) {
    const float* x       = (const float*)d_in[0];
    const float* feature = (const float*)d_in[1];
    const float* weight  = (const float*)d_in[2];
    const float* t0      = (const float*)d_in[3];
    const float* t1      = (const float*)d_in[4];
    const float* t2      = (const float*)d_in[5];
    const float* t3      = (const float*)d_in[6];
    const float* m0      = (const float*)d_in[7];
    const float* m1      = (const float*)d_in[8];
    const float* m2      = (const float*)d_in[9];
    const float* m3      = (const float*)d_in[10];
    const float* bias    = (const float*)d_in[11];
    const float* prelu_a = (const float*)d_in[12];
    float* out = (float*)d_out;

    front_kernel<<<FRONT_BLOCKS, 256>>>(x, feature, weight, t0, t1, t2, t3,
                                        m0, m1, m2, m3);
    {
        cudaFuncSetAttribute(deconv_mma_kernel,
                             cudaFuncAttributeMaxDynamicSharedMemorySize,
                             NSTG * STG_BYTES);
        dim3 grid(HW * HW / 128, 4, B_);     // 32 x 4 x 16
        deconv_mma_kernel<<<grid, 256, NSTG * STG_BYTES>>>(bias, prelu_a, out);
    }
}